// round 1
// baseline (speedup 1.0000x reference)
#include <cuda_runtime.h>
#include <cuda_bf16.h>
#include <cstdint>

// MXFP8 e4m3 block-32 quantize->dequantize.
// One thread handles one float4 (4 elems); 8 consecutive threads form one
// 32-element block. Block amax via 3 butterfly shuffles (xor 1,2,4 stay
// inside the 8-lane group). All scale math is exact powers of two done with
// exponent-bit manipulation, matching the reference arithmetic bit-exactly.

__global__ __launch_bounds__(256) void mxq_kernel(const float* __restrict__ x,
                                                  float* __restrict__ out,
                                                  int n4) {
    int i = blockIdx.x * blockDim.x + threadIdx.x;
    if (i >= n4) return;

    float4 v = reinterpret_cast<const float4*>(x)[i];

    // local amax over 4 elems
    float m = fmaxf(fmaxf(fabsf(v.x), fabsf(v.y)), fmaxf(fabsf(v.z), fabsf(v.w)));
    // reduce over the 8-lane group (lanes l, l^1, l^2, l^4 share a block)
    m = fmaxf(m, __shfl_xor_sync(0xffffffffu, m, 1));
    m = fmaxf(m, __shfl_xor_sync(0xffffffffu, m, 2));
    m = fmaxf(m, __shfl_xor_sync(0xffffffffu, m, 4));

    // shared_exp = floor(log2(amax)) - 8, clamped at -127.
    // floor(log2) for a normal float = biased_exp - 127.
    // amax denormal  -> floor(log2) <= -127, minus 8, clamp -> -127.
    // amax == 0      -> output is 0 regardless of scale; -127 path is fine.
    unsigned mb = __float_as_uint(m);          // m >= 0, no sign bit
    int ef = (int)(mb >> 23);
    int se = (ef == 0) ? -127 : (ef - 127 - 8);
    se = max(se, -127);

    // inv_scale = 2^-se  (se in [-127,119] -> exp field in [8,254], always normal)
    float inv_scale = __uint_as_float((unsigned)(127 - se) << 23);
    // scale = 2^se; se == -127 needs the denormal encoding 0x00400000
    float scale = (se >= -126) ? __uint_as_float((unsigned)(se + 127) << 23)
                               : __uint_as_float(0x00400000u);

    // per-element e4m3 quantize (denorms via pe clamp at -6),
    // round half away from zero, saturate at 448, rescale.
    auto q1 = [&](float a) -> float {
        float as = fabsf(a) * inv_scale;       // exact: power-of-two multiply
        unsigned b = __float_as_uint(as);
        int pe = (int)(b >> 23) - 127;         // denormal as -> very negative
        pe = max(pe, -6);                      // MIN_EXP clamp (also fixes denorms)
        // lshift = 2^(3-pe), inv = 2^(pe-3); pe in [-6, 9] -> both normal
        float lsh = __uint_as_float((unsigned)(3 - pe + 127) << 23);
        float ils = __uint_as_float((unsigned)(pe - 3 + 127) << 23);
        float q = floorf(as * lsh + 0.5f);     // round half away from zero (|.|)
        float d = fminf(q * ils, 448.0f);      // saturate e4m3 max norm
        return copysignf(d * scale, a);
    };

    float4 r;
    r.x = q1(v.x);
    r.y = q1(v.y);
    r.z = q1(v.z);
    r.w = q1(v.w);

    reinterpret_cast<float4*>(out)[i] = r;
}

extern "C" void kernel_launch(void* const* d_in, const int* in_sizes, int n_in,
                              void* d_out, int out_size) {
    const float* x = (const float*)d_in[0];
    float* out = (float*)d_out;
    int n = in_sizes[0];            // 8192*8192, divisible by 4
    int n4 = n >> 2;
    int threads = 256;
    int blocks = (n4 + threads - 1) / threads;
    mxq_kernel<<<blocks, threads>>>(x, out, n4);
}

// round 6
// speedup vs baseline: 1.0427x; 1.0427x over previous
#include <cuda_runtime.h>
#include <cuda_bf16.h>
#include <cstdint>

// MXFP8 e4m3 block-32 quantize->dequantize.
// One thread handles TWO float4 tiles (8 elems) from two adjacent 256-thread
// spans, giving 2 independent outstanding LDG.128s per thread before any
// dependent shuffle work. 8 consecutive threads form one 32-element block;
// block amax via 3 butterfly shuffles (xor 1,2,4). All scale math is exact
// powers of two via exponent-bit manipulation (bit-exact vs the reference).

__device__ __forceinline__ float blk_scale_pair(float m, float& inv_scale) {
    // shared_exp = floor(log2(amax)) - 8, clamped at -127.
    unsigned mb = __float_as_uint(m);
    int ef = (int)(mb >> 23);
    int se = (ef == 0) ? -127 : (ef - 127 - 8);
    se = max(se, -127);
    inv_scale = __uint_as_float((unsigned)(127 - se) << 23);
    return (se >= -126) ? __uint_as_float((unsigned)(se + 127) << 23)
                        : __uint_as_float(0x00400000u);   // 2^-127 denormal
}

__device__ __forceinline__ float q1(float a, float inv_scale, float scale) {
    float as = fabsf(a) * inv_scale;           // exact: power-of-two multiply
    unsigned b = __float_as_uint(as);
    int pe = (int)(b >> 23) - 127;             // denormal 'as' -> very negative
    pe = max(pe, -6);                          // MIN_EXP clamp (covers denorms)
    float lsh = __uint_as_float((unsigned)(3 - pe + 127) << 23);   // 2^(3-pe)
    float ils = __uint_as_float((unsigned)(pe - 3 + 127) << 23);   // 2^(pe-3)
    float q = floorf(as * lsh + 0.5f);         // round half away from zero
    float d = fminf(q * ils, 448.0f);          // saturate e4m3 max norm
    return copysignf(d * scale, a);
}

__global__ __launch_bounds__(256) void mxq_kernel(const float4* __restrict__ x,
                                                  float4* __restrict__ out,
                                                  int n4) {
    int i0 = blockIdx.x * 512 + threadIdx.x;   // tile A
    int i1 = i0 + 256;                         // tile B (independent load)
    bool p0 = i0 < n4, p1 = i1 < n4;

    float4 v0, v1;
    if (p0) v0 = __ldcs(x + i0);               // streaming: evict-first
    if (p1) v1 = __ldcs(x + i1);

    // local amax, then 8-lane group reduce — the two chains interleave
    float m0 = fmaxf(fmaxf(fabsf(v0.x), fabsf(v0.y)), fmaxf(fabsf(v0.z), fabsf(v0.w)));
    float m1 = fmaxf(fmaxf(fabsf(v1.x), fabsf(v1.y)), fmaxf(fabsf(v1.z), fabsf(v1.w)));
    m0 = fmaxf(m0, __shfl_xor_sync(0xffffffffu, m0, 1));
    m1 = fmaxf(m1, __shfl_xor_sync(0xffffffffu, m1, 1));
    m0 = fmaxf(m0, __shfl_xor_sync(0xffffffffu, m0, 2));
    m1 = fmaxf(m1, __shfl_xor_sync(0xffffffffu, m1, 2));
    m0 = fmaxf(m0, __shfl_xor_sync(0xffffffffu, m0, 4));
    m1 = fmaxf(m1, __shfl_xor_sync(0xffffffffu, m1, 4));

    float is0, is1;
    float s0 = blk_scale_pair(m0, is0);
    float s1 = blk_scale_pair(m1, is1);

    if (p0) {
        float4 r;
        r.x = q1(v0.x, is0, s0); r.y = q1(v0.y, is0, s0);
        r.z = q1(v0.z, is0, s0); r.w = q1(v0.w, is0, s0);
        __stcs(out + i0, r);
    }
    if (p1) {
        float4 r;
        r.x = q1(v1.x, is1, s1); r.y = q1(v1.y, is1, s1);
        r.z = q1(v1.z, is1, s1); r.w = q1(v1.w, is1, s1);
        __stcs(out + i1, r);
    }
}

extern "C" void kernel_launch(void* const* d_in, const int* in_sizes, int n_in,
                              void* d_out, int out_size) {
    const float4* x = (const float4*)d_in[0];
    float4* out = (float4*)d_out;
    int n = in_sizes[0];            // 8192*8192, divisible by 4
    int n4 = n >> 2;
    int blocks = (n4 + 511) / 512;  // 512 float4s (two 256-tiles) per block
    mxq_kernel<<<blocks, 256>>>(x, out, n4);
}